// round 4
// baseline (speedup 1.0000x reference)
#include <cuda_runtime.h>
#include <cuda_fp16.h>

#define NMAX 100000
#define EMAX 1600000
#define CMAX 128

// Scratch (__device__ globals: allocation-free rule)
__device__ __half d_G[(size_t)NMAX * CMAX];       // messages (half)
__device__ float  d_B1[(size_t)NMAX * CMAX];      // layer activations (fp32)
__device__ float  d_B2[(size_t)NMAX * CMAX];
__device__ float  d_dinv[NMAX];
__device__ int    d_cnt[NMAX];
__device__ int    d_cur[NMAX];
__device__ int    d_off[NMAX + 1];
__device__ int    d_csr[EMAX];
__device__ int    d_blk[128];
__device__ int    d_blk2[128];
__device__ unsigned d_gmin[64];

#define FMA2(d, a, b, c) \
    asm("fma.rn.f32x2 %0, %1, %2, %3;" : "=l"(d) : "l"(a), "l"(b), "l"(c))
#define PACK2(d, x) \
    asm("mov.b64 %0, {%1, %1};" : "=l"(d) : "f"(x))
#define UNPACK2(lo, hi, v) \
    asm("mov.b64 {%0, %1}, %2;" : "=f"(lo), "=f"(hi) : "l"(v))

__device__ __forceinline__ unsigned enc_f(float f) {
    unsigned u = __float_as_uint(f);
    return (u & 0x80000000u) ? ~u : (u | 0x80000000u);
}
__device__ __forceinline__ float dec_f(unsigned e) {
    unsigned u = (e & 0x80000000u) ? (e ^ 0x80000000u) : ~e;
    return __uint_as_float(u);
}

// ================= CSR build =================
__global__ void k_scan1(int N) {
    __shared__ int sh[256];
    int t = threadIdx.x;
    int base = blockIdx.x * 1024 + t * 4;
    int c0 = 0, c1 = 0, c2 = 0, c3 = 0;
    if (base + 3 < N) {
        int4 v = *(const int4*)&d_cnt[base];
        c0 = v.x; c1 = v.y; c2 = v.z; c3 = v.w;
    } else {
        if (base + 0 < N) c0 = d_cnt[base + 0];
        if (base + 1 < N) c1 = d_cnt[base + 1];
        if (base + 2 < N) c2 = d_cnt[base + 2];
        if (base + 3 < N) c3 = d_cnt[base + 3];
    }
    int s = c0 + c1 + c2 + c3;
    sh[t] = s;
    __syncthreads();
    for (int d = 1; d < 256; d <<= 1) {
        int v = (t >= d) ? sh[t - d] : 0;
        __syncthreads();
        sh[t] += v;
        __syncthreads();
    }
    int excl = sh[t] - s;
    if (base + 0 < N) d_off[base + 0] = excl;
    if (base + 1 < N) d_off[base + 1] = excl + c0;
    if (base + 2 < N) d_off[base + 2] = excl + c0 + c1;
    if (base + 3 < N) d_off[base + 3] = excl + c0 + c1 + c2;
    if (t == 255) d_blk[blockIdx.x] = sh[255];
}

__global__ void k_scan2(int nblk) {
    __shared__ int sh[128];
    int t = threadIdx.x;
    int v = (t < nblk) ? d_blk[t] : 0;
    sh[t] = v;
    __syncthreads();
    for (int d = 1; d < 128; d <<= 1) {
        int u = (t >= d) ? sh[t - d] : 0;
        __syncthreads();
        sh[t] += u;
        __syncthreads();
    }
    d_blk2[t] = sh[t] - v;
}

__global__ void k_scan3(int N, int E) {
    int i = blockIdx.x * blockDim.x + threadIdx.x;
    if (i < N) {
        d_off[i] += d_blk2[i >> 10];
        d_dinv[i] = rsqrtf((float)d_cnt[i] + 1.0f);  // +1 self-loop
        d_cur[i] = 0;
    }
    if (i == 0) d_off[N] = E;
    if (blockIdx.x == 0 && threadIdx.x < 64) d_gmin[threadIdx.x] = 0xFFFFFFFFu;
}

// rescale layer-1 messages by dinv (gemm1 ran before dinv existed) + CSR fill fused.
// A row of G is 128 halves = 256 bytes = 16 uint4 words.
__global__ void k_rescale(__half* __restrict__ g, int N,
                          const int* __restrict__ src, const int* __restrict__ dst, int E)
{
    int i = blockIdx.x * blockDim.x + threadIdx.x;
    int n4 = N * 16;                       // uint4 words in G
    if (i < n4) {
        int row = i >> 4;
        float dv = d_dinv[row];
        uint4 v = ((const uint4*)g)[i];
        __half2* h = (__half2*)&v;
#pragma unroll
        for (int k = 0; k < 4; k++) {
            float2 f = __half22float2(h[k]);
            h[k] = __floats2half2_rn(f.x * dv, f.y * dv);
        }
        ((uint4*)g)[i] = v;
    }
    int fi = i - n4;
    if (fi >= 0 && fi < E) {
        int d = dst[fi];
        int p = atomicAdd(&d_cur[d], 1);
        d_csr[d_off[d] + p] = src[fi];
    }
}

// ================= GEMM: g[row] = half(scale * (A[row] @ W)) =================
// 128 threads; each computes an 8x8 tile via fma.rn.f32x2.
// HIST: blocks beyond gemmBlocks do the degree histogram instead.
// DINV: epilogue multiplies by d_dinv[row] (false for layer 1, rescaled later).
template <int COLS, int TROWS, bool HIST, bool DINV>
__global__ void __launch_bounds__(128)
k_gemm(const float* __restrict__ A, const float* __restrict__ W,
       __half* __restrict__ g, int N,
       const int* __restrict__ dstp, int E, int gemmBlocks)
{
    if (HIST && (int)blockIdx.x >= gemmBlocks) {
        int nb = gridDim.x - gemmBlocks;
        for (int i = (blockIdx.x - gemmBlocks) * 128 + threadIdx.x; i < E; i += nb * 128)
            atomicAdd(&d_cnt[dstp[i]], 1);
        return;
    }
    extern __shared__ float sm[];
    constexpr int RS = TROWS + 4;
    float* Xs = sm;               // [128][RS] transposed (k-major, row-fast)
    float* Ws = sm + 128 * RS;    // [128][COLS]
    constexpr int CG = COLS / 8;
    const int tid = threadIdx.x;
    const int cg = tid % CG;
    const int rg = tid / CG;
    const int base = blockIdx.x * TROWS;

    for (int i = tid; i < 128 * COLS / 4; i += 128)
        ((float4*)Ws)[i] = __ldg((const float4*)W + i);

    for (int i = tid; i < TROWS * 32; i += 128) {
        int r = i % TROWS;
        int k4 = i / TROWS;
        int row = base + r;
        float4 v = make_float4(0.f, 0.f, 0.f, 0.f);
        if (row < N) v = __ldg((const float4*)(A + (size_t)row * 128) + k4);
        int k = k4 * 4;
        Xs[(k + 0) * RS + r] = v.x;
        Xs[(k + 1) * RS + r] = v.y;
        Xs[(k + 2) * RS + r] = v.z;
        Xs[(k + 3) * RS + r] = v.w;
    }
    __syncthreads();

    unsigned long long acc[8][4];
#pragma unroll
    for (int r = 0; r < 8; r++)
#pragma unroll
        for (int c = 0; c < 4; c++) acc[r][c] = 0ull;

#pragma unroll 4
    for (int k = 0; k < 128; k++) {
        float4 xa = *(const float4*)&Xs[k * RS + rg * 8];
        float4 xb = *(const float4*)&Xs[k * RS + rg * 8 + 4];
        float xr[8] = {xa.x, xa.y, xa.z, xa.w, xb.x, xb.y, xb.z, xb.w};
        unsigned long long x2[8];
#pragma unroll
        for (int r = 0; r < 8; r++) PACK2(x2[r], xr[r]);
        ulonglong2 wA = *(const ulonglong2*)&Ws[k * COLS + cg * 8];
        ulonglong2 wB = *(const ulonglong2*)&Ws[k * COLS + cg * 8 + 4];
        unsigned long long w2[4] = {wA.x, wA.y, wB.x, wB.y};
#pragma unroll
        for (int r = 0; r < 8; r++)
#pragma unroll
            for (int c = 0; c < 4; c++) FMA2(acc[r][c], x2[r], w2[c], acc[r][c]);
    }

#pragma unroll
    for (int r = 0; r < 8; r++) {
        int row = base + rg * 8 + r;
        if (row < N) {
            float dv = DINV ? d_dinv[row] : 1.0f;
            __half2 h[4];
#pragma unroll
            for (int c = 0; c < 4; c++) {
                float lo, hi;
                UNPACK2(lo, hi, acc[r][c]);
                h[c] = __floats2half2_rn(lo * dv, hi * dv);
            }
            *(uint4*)(g + (size_t)row * COLS + cg * 8) = *(uint4*)h;
        }
    }
}

// ================= CSR aggregate (half messages, fp32 accumulate) =================
__device__ __forceinline__ void add_h8(float* a, uint4 v) {
    float2 f0 = __half22float2(*(__half2*)&v.x);
    float2 f1 = __half22float2(*(__half2*)&v.y);
    float2 f2 = __half22float2(*(__half2*)&v.z);
    float2 f3 = __half22float2(*(__half2*)&v.w);
    a[0] += f0.x; a[1] += f0.y; a[2] += f1.x; a[3] += f1.y;
    a[4] += f2.x; a[5] += f2.y; a[6] += f3.x; a[7] += f3.y;
}

// layers 1&2: COLS=128 (16 uint4/row), 16 lanes/node, relu(dinv*sum + bias) -> fp32 out
__global__ void k_agg128(const __half* __restrict__ g, const float* __restrict__ bias,
                         float* __restrict__ out, int N)
{
    int idx = blockIdx.x * blockDim.x + threadIdx.x;
    int node = idx >> 4;
    int lane = idx & 15;
    if (node >= N) return;
    const uint4* gp = (const uint4*)g;
    float a[8] = {0, 0, 0, 0, 0, 0, 0, 0};
    add_h8(a, __ldg(&gp[(size_t)node * 16 + lane]));       // self-loop
    int s = d_off[node], e = d_off[node + 1];
    int j = s;
    for (; j + 4 <= e; j += 4) {
        int n0 = d_csr[j], n1 = d_csr[j + 1], n2 = d_csr[j + 2], n3 = d_csr[j + 3];
        uint4 v0 = __ldg(&gp[(size_t)n0 * 16 + lane]);
        uint4 v1 = __ldg(&gp[(size_t)n1 * 16 + lane]);
        uint4 v2 = __ldg(&gp[(size_t)n2 * 16 + lane]);
        uint4 v3 = __ldg(&gp[(size_t)n3 * 16 + lane]);
        add_h8(a, v0); add_h8(a, v1); add_h8(a, v2); add_h8(a, v3);
    }
    for (; j < e; j++)
        add_h8(a, __ldg(&gp[(size_t)d_csr[j] * 16 + lane]));

    float dv = d_dinv[node];
    float4 b0 = __ldg((const float4*)bias + lane * 2);
    float4 b1 = __ldg((const float4*)bias + lane * 2 + 1);
    float r[8];
    r[0] = fmaxf(fmaf(a[0], dv, b0.x), 0.f);
    r[1] = fmaxf(fmaf(a[1], dv, b0.y), 0.f);
    r[2] = fmaxf(fmaf(a[2], dv, b0.z), 0.f);
    r[3] = fmaxf(fmaf(a[3], dv, b0.w), 0.f);
    r[4] = fmaxf(fmaf(a[4], dv, b1.x), 0.f);
    r[5] = fmaxf(fmaf(a[5], dv, b1.y), 0.f);
    r[6] = fmaxf(fmaf(a[6], dv, b1.z), 0.f);
    r[7] = fmaxf(fmaf(a[7], dv, b1.w), 0.f);
    float* p = out + (size_t)node * 128 + lane * 8;
    *(float4*)p = make_float4(r[0], r[1], r[2], r[3]);
    *(float4*)(p + 4) = make_float4(r[4], r[5], r[6], r[7]);
}

// layer 3: COLS=64 (8 uint4/row), 8 lanes/node, fused min-pool (bias deferred)
__global__ void k_agg64min(const __half* __restrict__ g, int N)
{
    __shared__ unsigned sMin[64];
    int tid = threadIdx.x;
    if (tid < 64) sMin[tid] = 0xFFFFFFFFu;
    __syncthreads();

    int idx = blockIdx.x * blockDim.x + tid;
    int node = idx >> 3;
    int lane = idx & 7;
    if (node < N) {
        const uint4* gp = (const uint4*)g;
        float a[8] = {0, 0, 0, 0, 0, 0, 0, 0};
        add_h8(a, __ldg(&gp[(size_t)node * 8 + lane]));
        int s = d_off[node], e = d_off[node + 1];
        int j = s;
        for (; j + 4 <= e; j += 4) {
            int n0 = d_csr[j], n1 = d_csr[j + 1], n2 = d_csr[j + 2], n3 = d_csr[j + 3];
            uint4 v0 = __ldg(&gp[(size_t)n0 * 8 + lane]);
            uint4 v1 = __ldg(&gp[(size_t)n1 * 8 + lane]);
            uint4 v2 = __ldg(&gp[(size_t)n2 * 8 + lane]);
            uint4 v3 = __ldg(&gp[(size_t)n3 * 8 + lane]);
            add_h8(a, v0); add_h8(a, v1); add_h8(a, v2); add_h8(a, v3);
        }
        for (; j < e; j++)
            add_h8(a, __ldg(&gp[(size_t)d_csr[j] * 8 + lane]));
        float dv = d_dinv[node];
#pragma unroll
        for (int i = 0; i < 8; i++)
            atomicMin(&sMin[lane * 8 + i], enc_f(a[i] * dv));
    }
    __syncthreads();
    if (tid < 64) atomicMin(&d_gmin[tid], sMin[tid]);
}

__global__ void k_final(const float* __restrict__ b3, float* __restrict__ out) {
    int c = threadIdx.x;
    out[c] = dec_f(d_gmin[c]) + b3[c];
}

extern "C" void kernel_launch(void* const* d_in, const int* in_sizes, int n_in,
                              void* d_out, int out_size)
{
    const float* x  = (const float*)d_in[0];
    const int*   ei = (const int*)d_in[1];
    const float* W1 = (const float*)d_in[2];
    const float* b1 = (const float*)d_in[3];
    const float* W2 = (const float*)d_in[4];
    const float* b2 = (const float*)d_in[5];
    const float* W3 = (const float*)d_in[6];
    const float* b3 = (const float*)d_in[7];
    float* out = (float*)d_out;

    int N = in_sizes[0] / 128;
    int E = in_sizes[1] / 2;
    const int* src = ei;
    const int* dst = ei + E;

    float *B1, *B2;
    __half* G;
    void* cntp;
    cudaGetSymbolAddress((void**)&B1, d_B1);
    cudaGetSymbolAddress((void**)&B2, d_B2);
    cudaGetSymbolAddress((void**)&G, d_G);
    cudaGetSymbolAddress(&cntp, d_cnt);

    const int smem = (128 * (64 + 4) + 128 * 128) * 4;   // == (128*(128+4)+128*64)*4
    cudaFuncSetAttribute(k_gemm<128, 64, true,  false>, cudaFuncAttributeMaxDynamicSharedMemorySize, smem);
    cudaFuncSetAttribute(k_gemm<128, 64, false, true>,  cudaFuncAttributeMaxDynamicSharedMemorySize, smem);
    cudaFuncSetAttribute(k_gemm<64, 128, false, true>,  cudaFuncAttributeMaxDynamicSharedMemorySize, smem);

    cudaMemsetAsync(cntp, 0, (size_t)N * sizeof(int));

    // Layer-1 GEMM (unscaled epilogue) fused with degree histogram
    int gb1 = (N + 63) / 64;
    k_gemm<128, 64, true, false><<<gb1 + 1024, 128, smem>>>(x, W1, G, N, dst, E, gb1);

    // CSR scans (dinv computed in scan3)
    int nblk = (N + 1023) / 1024;
    k_scan1<<<nblk, 256>>>(N);
    k_scan2<<<1, 128>>>(nblk);
    k_scan3<<<(N + 255) / 256, 256>>>(N, E);

    // Rescale layer-1 messages by dinv, fused with CSR fill
    int n4 = N * 16;
    k_rescale<<<(n4 + E + 255) / 256, 256>>>(G, N, src, dst, E);

    // Layer 1 aggregate
    k_agg128<<<(N * 16 + 255) / 256, 256>>>(G, b1, B2, N);

    // Layer 2
    k_gemm<128, 64, false, true><<<(N + 63) / 64, 128, smem>>>(B2, W2, G, N, nullptr, 0, 1 << 30);
    k_agg128<<<(N * 16 + 255) / 256, 256>>>(G, b2, B1, N);

    // Layer 3 (64 cols) + fused min-pool
    k_gemm<64, 128, false, true><<<(N + 127) / 128, 128, smem>>>(B1, W3, G, N, nullptr, 0, 1 << 30);
    k_agg64min<<<(N * 8 + 255) / 256, 256>>>(G, N);

    k_final<<<1, 64>>>(b3, out);
}

// round 5
// speedup vs baseline: 1.2703x; 1.2703x over previous
#include <cuda_runtime.h>
#include <cuda_fp16.h>

#define NMAX 100000
#define EMAX 1600000
#define CMAX 128

// Scratch (__device__ globals: allocation-free rule)
__device__ __half d_G[(size_t)NMAX * CMAX];       // messages (half)
__device__ float  d_B1[(size_t)NMAX * CMAX];      // layer activations (fp32)
__device__ float  d_B2[(size_t)NMAX * CMAX];
__device__ float  d_dinv[NMAX];
__device__ int    d_cnt[NMAX];
__device__ int    d_cur[NMAX];
__device__ int    d_off[NMAX + 1];
__device__ int    d_csr[EMAX];
__device__ int    d_blk[128];
__device__ int    d_blk2[128];
__device__ unsigned d_gmin[64];

#define FMA2(d, a, b, c) \
    asm("fma.rn.f32x2 %0, %1, %2, %3;" : "=l"(d) : "l"(a), "l"(b), "l"(c))
#define PACK2(d, x) \
    asm("mov.b64 %0, {%1, %1};" : "=l"(d) : "f"(x))
#define UNPACK2(lo, hi, v) \
    asm("mov.b64 {%0, %1}, %2;" : "=f"(lo), "=f"(hi) : "l"(v))

__device__ __forceinline__ unsigned enc_f(float f) {
    unsigned u = __float_as_uint(f);
    return (u & 0x80000000u) ? ~u : (u | 0x80000000u);
}
__device__ __forceinline__ float dec_f(unsigned e) {
    unsigned u = (e & 0x80000000u) ? (e ^ 0x80000000u) : ~e;
    return __uint_as_float(u);
}

// ================= degree histogram =================
__global__ void k_hist(const int* __restrict__ dst, int E) {
    int i = blockIdx.x * blockDim.x + threadIdx.x;
    if (i < E) atomicAdd(&d_cnt[dst[i]], 1);
}

// ================= CSR scans =================
__global__ void k_scan1(int N) {
    __shared__ int sh[256];
    int t = threadIdx.x;
    int base = blockIdx.x * 1024 + t * 4;
    int c0 = 0, c1 = 0, c2 = 0, c3 = 0;
    if (base + 3 < N) {
        int4 v = *(const int4*)&d_cnt[base];
        c0 = v.x; c1 = v.y; c2 = v.z; c3 = v.w;
    } else {
        if (base + 0 < N) c0 = d_cnt[base + 0];
        if (base + 1 < N) c1 = d_cnt[base + 1];
        if (base + 2 < N) c2 = d_cnt[base + 2];
        if (base + 3 < N) c3 = d_cnt[base + 3];
    }
    int s = c0 + c1 + c2 + c3;
    sh[t] = s;
    __syncthreads();
    for (int d = 1; d < 256; d <<= 1) {
        int v = (t >= d) ? sh[t - d] : 0;
        __syncthreads();
        sh[t] += v;
        __syncthreads();
    }
    int excl = sh[t] - s;
    if (base + 0 < N) d_off[base + 0] = excl;
    if (base + 1 < N) d_off[base + 1] = excl + c0;
    if (base + 2 < N) d_off[base + 2] = excl + c0 + c1;
    if (base + 3 < N) d_off[base + 3] = excl + c0 + c1 + c2;
    if (t == 255) d_blk[blockIdx.x] = sh[255];
}

__global__ void k_scan2(int nblk) {
    __shared__ int sh[128];
    int t = threadIdx.x;
    int v = (t < nblk) ? d_blk[t] : 0;
    sh[t] = v;
    __syncthreads();
    for (int d = 1; d < 128; d <<= 1) {
        int u = (t >= d) ? sh[t - d] : 0;
        __syncthreads();
        sh[t] += u;
        __syncthreads();
    }
    d_blk2[t] = sh[t] - v;
}

// Also: computes dinv, zeroes d_cnt/d_cur for the next graph replay, inits gmin.
__global__ void k_scan3(int N, int E) {
    int i = blockIdx.x * blockDim.x + threadIdx.x;
    if (i < N) {
        d_off[i] += d_blk2[i >> 10];
        d_dinv[i] = rsqrtf((float)d_cnt[i] + 1.0f);  // +1 self-loop
        d_cnt[i] = 0;                                 // self-clean for replay
        d_cur[i] = 0;
    }
    if (i == 0) d_off[N] = E;
    if (blockIdx.x == 0 && threadIdx.x < 64) d_gmin[threadIdx.x] = 0xFFFFFFFFu;
}

// ================= GEMM: g[row] = half(dinv[row] * (A[row] @ W)) =================
// 128 threads; each computes an 8x8 tile via fma.rn.f32x2.
// FILL: blocks with bid < fillBlocks do the CSR fill instead (low bids -> start
// in the first wave, overlapping the GEMM). dinv is ready (scan3 ran earlier).
template <int COLS, int TROWS, bool FILL>
__global__ void __launch_bounds__(128)
k_gemm(const float* __restrict__ A, const float* __restrict__ W,
       __half* __restrict__ g, int N,
       const int* __restrict__ src, const int* __restrict__ dstp, int E, int fillBlocks)
{
    if (FILL && (int)blockIdx.x < fillBlocks) {
        for (int i = blockIdx.x * 128 + threadIdx.x; i < E; i += fillBlocks * 128) {
            int d = dstp[i];
            int p = atomicAdd(&d_cur[d], 1);
            d_csr[d_off[d] + p] = src[i];
        }
        return;
    }
    extern __shared__ float sm[];
    constexpr int RS = TROWS + 4;
    float* Xs = sm;               // [128][RS] transposed (k-major, row-fast)
    float* Ws = sm + 128 * RS;    // [128][COLS]
    constexpr int CG = COLS / 8;
    const int tid = threadIdx.x;
    const int cg = tid % CG;
    const int rg = tid / CG;
    const int base = (blockIdx.x - (FILL ? fillBlocks : 0)) * TROWS;

    for (int i = tid; i < 128 * COLS / 4; i += 128)
        ((float4*)Ws)[i] = __ldg((const float4*)W + i);

    for (int i = tid; i < TROWS * 32; i += 128) {
        int r = i % TROWS;
        int k4 = i / TROWS;
        int row = base + r;
        float4 v = make_float4(0.f, 0.f, 0.f, 0.f);
        if (row < N) v = __ldg((const float4*)(A + (size_t)row * 128) + k4);
        int k = k4 * 4;
        Xs[(k + 0) * RS + r] = v.x;
        Xs[(k + 1) * RS + r] = v.y;
        Xs[(k + 2) * RS + r] = v.z;
        Xs[(k + 3) * RS + r] = v.w;
    }
    __syncthreads();

    unsigned long long acc[8][4];
#pragma unroll
    for (int r = 0; r < 8; r++)
#pragma unroll
        for (int c = 0; c < 4; c++) acc[r][c] = 0ull;

#pragma unroll 4
    for (int k = 0; k < 128; k++) {
        float4 xa = *(const float4*)&Xs[k * RS + rg * 8];
        float4 xb = *(const float4*)&Xs[k * RS + rg * 8 + 4];
        float xr[8] = {xa.x, xa.y, xa.z, xa.w, xb.x, xb.y, xb.z, xb.w};
        unsigned long long x2[8];
#pragma unroll
        for (int r = 0; r < 8; r++) PACK2(x2[r], xr[r]);
        ulonglong2 wA = *(const ulonglong2*)&Ws[k * COLS + cg * 8];
        ulonglong2 wB = *(const ulonglong2*)&Ws[k * COLS + cg * 8 + 4];
        unsigned long long w2[4] = {wA.x, wA.y, wB.x, wB.y};
#pragma unroll
        for (int r = 0; r < 8; r++)
#pragma unroll
            for (int c = 0; c < 4; c++) FMA2(acc[r][c], x2[r], w2[c], acc[r][c]);
    }

#pragma unroll
    for (int r = 0; r < 8; r++) {
        int row = base + rg * 8 + r;
        if (row < N) {
            float dv = d_dinv[row];
            __half2 h[4];
#pragma unroll
            for (int c = 0; c < 4; c++) {
                float lo, hi;
                UNPACK2(lo, hi, acc[r][c]);
                h[c] = __floats2half2_rn(lo * dv, hi * dv);
            }
            *(uint4*)(g + (size_t)row * COLS + cg * 8) = *(uint4*)h;
        }
    }
}

// ================= CSR aggregate (half messages, fp32 accum, 1 warp/node) ========
// layers 1&2: COLS=128 -> row = 32 uint2 words; lane loads uint2 (cols 4*lane..+3)
__global__ void k_agg128(const __half* __restrict__ g, const float* __restrict__ bias,
                         float* __restrict__ out, int N)
{
    int node = (blockIdx.x * blockDim.x + threadIdx.x) >> 5;
    int lane = threadIdx.x & 31;
    if (node >= N) return;
    const uint2* gp = (const uint2*)g;

    float a0 = 0.f, a1 = 0.f, a2 = 0.f, a3 = 0.f;
    {
        uint2 v = __ldg(&gp[(size_t)node * 32 + lane]);  // self-loop
        float2 f0 = __half22float2(*(__half2*)&v.x);
        float2 f1 = __half22float2(*(__half2*)&v.y);
        a0 += f0.x; a1 += f0.y; a2 += f1.x; a3 += f1.y;
    }
    int s = d_off[node], e = d_off[node + 1];
    int j = s;
    for (; j + 4 <= e; j += 4) {
        int n0 = d_csr[j], n1 = d_csr[j + 1], n2 = d_csr[j + 2], n3 = d_csr[j + 3];
        uint2 v0 = __ldg(&gp[(size_t)n0 * 32 + lane]);
        uint2 v1 = __ldg(&gp[(size_t)n1 * 32 + lane]);
        uint2 v2 = __ldg(&gp[(size_t)n2 * 32 + lane]);
        uint2 v3 = __ldg(&gp[(size_t)n3 * 32 + lane]);
        float2 f;
        f = __half22float2(*(__half2*)&v0.x); a0 += f.x; a1 += f.y;
        f = __half22float2(*(__half2*)&v0.y); a2 += f.x; a3 += f.y;
        f = __half22float2(*(__half2*)&v1.x); a0 += f.x; a1 += f.y;
        f = __half22float2(*(__half2*)&v1.y); a2 += f.x; a3 += f.y;
        f = __half22float2(*(__half2*)&v2.x); a0 += f.x; a1 += f.y;
        f = __half22float2(*(__half2*)&v2.y); a2 += f.x; a3 += f.y;
        f = __half22float2(*(__half2*)&v3.x); a0 += f.x; a1 += f.y;
        f = __half22float2(*(__half2*)&v3.y); a2 += f.x; a3 += f.y;
    }
    for (; j < e; j++) {
        uint2 v = __ldg(&gp[(size_t)d_csr[j] * 32 + lane]);
        float2 f0 = __half22float2(*(__half2*)&v.x);
        float2 f1 = __half22float2(*(__half2*)&v.y);
        a0 += f0.x; a1 += f0.y; a2 += f1.x; a3 += f1.y;
    }

    float dv = d_dinv[node];
    float4 b = __ldg((const float4*)bias + lane);
    float4 r;
    r.x = fmaxf(fmaf(a0, dv, b.x), 0.f);
    r.y = fmaxf(fmaf(a1, dv, b.y), 0.f);
    r.z = fmaxf(fmaf(a2, dv, b.z), 0.f);
    r.w = fmaxf(fmaf(a3, dv, b.w), 0.f);
    ((float4*)out)[(size_t)node * 32 + lane] = r;
}

// layer 3: COLS=64 -> row = 32 half2 words; lane covers cols {2*lane, 2*lane+1}.
// Fused min-pool (bias deferred to k_final).
__global__ void k_agg64min(const __half* __restrict__ g, int N)
{
    __shared__ unsigned sMin[64];
    int tid = threadIdx.x;
    if (tid < 64) sMin[tid] = 0xFFFFFFFFu;
    __syncthreads();

    int node = (blockIdx.x * blockDim.x + tid) >> 5;
    int lane = tid & 31;
    if (node < N) {
        const unsigned* gp = (const unsigned*)g;
        float a0 = 0.f, a1 = 0.f;
        {
            unsigned v = __ldg(&gp[(size_t)node * 32 + lane]);
            float2 f = __half22float2(*(__half2*)&v);
            a0 += f.x; a1 += f.y;
        }
        int s = d_off[node], e = d_off[node + 1];
        int j = s;
        for (; j + 4 <= e; j += 4) {
            int n0 = d_csr[j], n1 = d_csr[j + 1], n2 = d_csr[j + 2], n3 = d_csr[j + 3];
            unsigned v0 = __ldg(&gp[(size_t)n0 * 32 + lane]);
            unsigned v1 = __ldg(&gp[(size_t)n1 * 32 + lane]);
            unsigned v2 = __ldg(&gp[(size_t)n2 * 32 + lane]);
            unsigned v3 = __ldg(&gp[(size_t)n3 * 32 + lane]);
            float2 f;
            f = __half22float2(*(__half2*)&v0); a0 += f.x; a1 += f.y;
            f = __half22float2(*(__half2*)&v1); a0 += f.x; a1 += f.y;
            f = __half22float2(*(__half2*)&v2); a0 += f.x; a1 += f.y;
            f = __half22float2(*(__half2*)&v3); a0 += f.x; a1 += f.y;
        }
        for (; j < e; j++) {
            unsigned v = __ldg(&gp[(size_t)d_csr[j] * 32 + lane]);
            float2 f = __half22float2(*(__half2*)&v);
            a0 += f.x; a1 += f.y;
        }
        float dv = d_dinv[node];
        atomicMin(&sMin[2 * lane + 0], enc_f(a0 * dv));
        atomicMin(&sMin[2 * lane + 1], enc_f(a1 * dv));
    }
    __syncthreads();
    if (tid < 64) atomicMin(&d_gmin[tid], sMin[tid]);
}

__global__ void k_final(const float* __restrict__ b3, float* __restrict__ out) {
    int c = threadIdx.x;
    out[c] = dec_f(d_gmin[c]) + b3[c];
}

extern "C" void kernel_launch(void* const* d_in, const int* in_sizes, int n_in,
                              void* d_out, int out_size)
{
    const float* x  = (const float*)d_in[0];
    const int*   ei = (const int*)d_in[1];
    const float* W1 = (const float*)d_in[2];
    const float* b1 = (const float*)d_in[3];
    const float* W2 = (const float*)d_in[4];
    const float* b2 = (const float*)d_in[5];
    const float* W3 = (const float*)d_in[6];
    const float* b3 = (const float*)d_in[7];
    float* out = (float*)d_out;

    int N = in_sizes[0] / 128;
    int E = in_sizes[1] / 2;
    const int* src = ei;
    const int* dst = ei + E;

    float *B1, *B2;
    __half* G;
    cudaGetSymbolAddress((void**)&B1, d_B1);
    cudaGetSymbolAddress((void**)&B2, d_B2);
    cudaGetSymbolAddress((void**)&G, d_G);

    const int smem = (128 * (64 + 4) + 128 * 128) * 4;   // == (128*(128+4)+128*64)*4
    cudaFuncSetAttribute(k_gemm<128, 64, true>,  cudaFuncAttributeMaxDynamicSharedMemorySize, smem);
    cudaFuncSetAttribute(k_gemm<128, 64, false>, cudaFuncAttributeMaxDynamicSharedMemorySize, smem);
    cudaFuncSetAttribute(k_gemm<64, 128, false>, cudaFuncAttributeMaxDynamicSharedMemorySize, smem);

    // CSR: hist + scans (dinv ready after scan3; cnt/cur self-cleaned there)
    k_hist<<<(E + 255) / 256, 256>>>(dst, E);
    int nblk = (N + 1023) / 1024;
    k_scan1<<<nblk, 256>>>(N);
    k_scan2<<<1, 128>>>(nblk);
    k_scan3<<<(N + 255) / 256, 256>>>(N, E);

    // Layer-1 GEMM with CSR fill fused at LOW block ids (overlaps first waves)
    const int fillBlocks = 1024;
    int gb1 = (N + 63) / 64;
    k_gemm<128, 64, true><<<gb1 + fillBlocks, 128, smem>>>(x, W1, G, N, src, dst, E, fillBlocks);
    k_agg128<<<(N * 32 + 255) / 256, 256>>>(G, b1, B2, N);

    // Layer 2
    k_gemm<128, 64, false><<<(N + 63) / 64, 128, smem>>>(B2, W2, G, N, nullptr, nullptr, 0, 0);
    k_agg128<<<(N * 32 + 255) / 256, 256>>>(G, b2, B1, N);

    // Layer 3 (64 cols) + fused min-pool
    k_gemm<64, 128, false><<<(N + 127) / 128, 128, smem>>>(B1, W3, G, N, nullptr, nullptr, 0, 0);
    k_agg64min<<<(N * 32 + 255) / 256, 256>>>(G, N);

    k_final<<<1, 64>>>(b3, out);
}